// round 13
// baseline (speedup 1.0000x reference)
#include <cuda_runtime.h>

#define DZ 64
#define HH 512
#define WW 512
#define PAD 5
#define TILE_H 32
#define NT 128                                  // 4 warps/block
#define NSTRIP 2
#define ROWTILES (HH / TILE_H)                  // 16
#define TOTAL_WARPS (DZ * ROWTILES * NSTRIP)    // 2048
#define NBLOCKS (TOTAL_WARPS / (NT / 32))       // 512
#define CPL 10                                  // columns per lane
#define NPAIR (CPL / 2)

// SSIM constants in raw-sum space (w = 1/121 cancels as w^4):
#define C1S 1.4641f      /* C1 * 121^2 */
#define C2S 13.1769f     /* C2 * 121^2 */

__device__ float g_partials[NBLOCKS];

typedef unsigned long long u64;
union F2 { u64 u; float2 f; };

__device__ __forceinline__ u64 f2add(u64 a, u64 b) {
    u64 d; asm("add.rn.f32x2 %0,%1,%2;" : "=l"(d) : "l"(a), "l"(b)); return d;
}
__device__ __forceinline__ u64 f2mul(u64 a, u64 b) {
    u64 d; asm("mul.rn.f32x2 %0,%1,%2;" : "=l"(d) : "l"(a), "l"(b)); return d;
}
__device__ __forceinline__ u64 f2fma(u64 a, u64 b, u64 c) {
    u64 d; asm("fma.rn.f32x2 %0,%1,%2,%3;" : "=l"(d) : "l"(a), "l"(b), "l"(c)); return d;
}

__device__ __forceinline__ u64 ldpair(const float* __restrict__ row, int c, bool ok) {
    F2 t;
    t.f = ok ? *reinterpret_cast<const float2*>(row + c) : make_float2(0.f, 0.f);
    return t.u;
}

// Vertical sliding-sum update for one input row (packed f32x2 per column pair).
template <int SGN>
__device__ __forceinline__ void vupdate(u64 vs[5][NPAIR],
                                        const float* __restrict__ xrow,
                                        const float* __restrict__ yrow,
                                        int cb) {
    const u64 NEG1 = 0xBF800000BF800000ULL;   // packed (-1.f, -1.f)
    #pragma unroll
    for (int k = 0; k < NPAIR; ++k) {
        int c = cb + 2 * k;                    // cb even -> pairs never straddle 0/512
        bool ok = ((unsigned)c < (unsigned)WW);
        u64 xv = ldpair(xrow, c, ok);
        u64 yv = ldpair(yrow, c, ok);
        if (SGN > 0) {
            vs[0][k] = f2add(vs[0][k], xv);
            vs[1][k] = f2add(vs[1][k], yv);
            vs[2][k] = f2fma(xv, xv, vs[2][k]);
            vs[3][k] = f2fma(yv, yv, vs[3][k]);
            vs[4][k] = f2fma(xv, yv, vs[4][k]);
        } else {
            u64 nx = f2mul(xv, NEG1);
            u64 ny = f2mul(yv, NEG1);
            vs[0][k] = f2add(vs[0][k], nx);
            vs[1][k] = f2add(vs[1][k], ny);
            vs[2][k] = f2fma(xv, nx, vs[2][k]);
            vs[3][k] = f2fma(yv, ny, vs[3][k]);
            vs[4][k] = f2fma(xv, ny, vs[4][k]);
        }
    }
}

__global__ __launch_bounds__(NT, 3)
void ssim_kernel(const float* __restrict__ X, const float* __restrict__ Y) {
    const int wid  = threadIdx.x >> 5;
    const int lane = threadIdx.x & 31;
    const int gw   = blockIdx.x * (NT / 32) + wid;

    const int s  = gw & 1;                    // strip (each block mixes A/B -> balanced)
    const int t  = gw >> 1;
    const int z  = t >> 4;
    const int row0 = (t & (ROWTILES - 1)) * TILE_H;

    // Strip A: vsum cols start at -6, outputs [0,309).
    // Strip B: vsum cols start at 304, outputs [309,512).
    const int W0  = s ? 304 : -6;
    const int OLO = s ? 309 : 0;
    const int OHI = s ? 512 : 309;

    const int cb = W0 + lane * CPL;           // even
    const float* __restrict__ Xz = X + (size_t)z * HH * WW;
    const float* __restrict__ Yz = Y + (size_t)z * HH * WW;

    // Vertical sliding sums: 5 channels x 5 packed column pairs.
    u64 vs[5][NPAIR];
    #pragma unroll
    for (int ch = 0; ch < 5; ++ch)
        #pragma unroll
        for (int k = 0; k < NPAIR; ++k) vs[ch][k] = 0ULL;

    // Prologue: rows [row0-5, row0+4] clamped to image.
    #pragma unroll 1
    for (int rr = row0 - PAD; rr < row0 + PAD; ++rr) {
        if (rr < 0 || rr >= HH) continue;
        vupdate<+1>(vs, Xz + (size_t)rr * WW, Yz + (size_t)rr * WW, cb);
    }

    float partial = 0.f;

    #pragma unroll 1
    for (int r = row0; r < row0 + TILE_H; ++r) {
        int rn = r + PAD;
        if (rn < HH)
            vupdate<+1>(vs, Xz + (size_t)rn * WW, Yz + (size_t)rn * WW, cb);
        int ro = r - PAD - 1;
        if (r > row0 && ro >= 0)
            vupdate<-1>(vs, Xz + (size_t)ro * WW, Yz + (size_t)ro * WW, cb);

        // Horizontal 11-tap sums, one-directional halo via prefix sums:
        // output col c = cb+5+j needs own cols cb+j..cb+9 (= T - P(j-1))
        // plus next lane's cols cb+10..cb+10+j (= shfl_down(P(j))).
        float Hs[5][CPL];
        #pragma unroll
        for (int ch = 0; ch < 5; ++ch) {
            float v[CPL];
            #pragma unroll
            for (int k = 0; k < NPAIR; ++k) {
                F2 tt; tt.u = vs[ch][k];
                v[2 * k] = tt.f.x; v[2 * k + 1] = tt.f.y;
            }
            float P[CPL];
            P[0] = v[0];
            #pragma unroll
            for (int j = 1; j < CPL; ++j) P[j] = P[j - 1] + v[j];
            float T = P[CPL - 1];
            #pragma unroll
            for (int j = 0; j < CPL; ++j) {
                float nP = __shfl_down_sync(0xFFFFFFFFu, P[j], 1);
                Hs[ch][j] = ((j == 0) ? T : (T - P[j - 1])) + nP;
            }
        }

        // SSIM in raw-sum space.
        #pragma unroll
        for (int j = 0; j < CPL; ++j) {
            float Sx  = Hs[0][j], Sy  = Hs[1][j];
            float Sxx = Hs[2][j], Syy = Hs[3][j], Sxy = Hs[4][j];
            float Pm = Sx * Sy;
            float Q  = fmaf(Sx, Sx, Sy * Sy);
            float n1 = fmaf(2.f, Pm, C1S);
            float n2 = fmaf(-2.f, Pm, fmaf(242.f, Sxy, C2S));
            float d1 = Q + C1S;
            float d2 = fmaf(121.f, Sxx + Syy, C2S - Q);
            float vv = __fdividef(n1 * n2, d1 * d2);
            int c = cb + PAD + j;
            if (c >= OLO && c < OHI) partial += vv;
        }
    }

    // Warp reduce, then one partial per block.
    #pragma unroll
    for (int off = 16; off > 0; off >>= 1)
        partial += __shfl_xor_sync(0xFFFFFFFFu, partial, off);
    __shared__ float wsum[NT / 32];
    if (lane == 0) wsum[wid] = partial;
    __syncthreads();
    if (threadIdx.x == 0)
        g_partials[blockIdx.x] = wsum[0] + wsum[1] + wsum[2] + wsum[3];
}

// One-warp finalize: 512 partials = 128 float4, 4 per lane, shfl reduce.
__global__ void finalize_kernel(float* out) {
    int lane = threadIdx.x;
    const float4* p = (const float4*)g_partials;
    double s = 0.0;
    #pragma unroll
    for (int i = 0; i < NBLOCKS / 4 / 32; ++i) {
        float4 v = p[lane + 32 * i];
        s += (double)v.x + (double)v.y + (double)v.z + (double)v.w;
    }
    #pragma unroll
    for (int off = 16; off > 0; off >>= 1)
        s += __shfl_xor_sync(0xFFFFFFFFu, s, off);
    if (lane == 0)
        out[0] = (float)(1.0 - s / (double)((size_t)DZ * HH * WW));
}

extern "C" void kernel_launch(void* const* d_in, const int* in_sizes, int n_in,
                              void* d_out, int out_size) {
    const float* x = (const float*)d_in[0];
    const float* y = (const float*)d_in[1];
    float* out = (float*)d_out;

    ssim_kernel<<<NBLOCKS, NT>>>(x, y);
    finalize_kernel<<<1, 32>>>(out);
}

// round 14
// speedup vs baseline: 1.0686x; 1.0686x over previous
#include <cuda_runtime.h>

#define DZ 64
#define HH 512
#define WW 512
#define PAD 5
#define TILE_H 32
#define NT 128                          // 4 warps per block
#define NSTRIP 3
#define ROWTILES (HH / TILE_H)          // 16
#define TOTAL_WARPS (DZ * ROWTILES * NSTRIP)   // 3072
#define NBLOCKS (TOTAL_WARPS / (NT/32))        // 768

// SSIM constants folded into raw-sum space (w = 1/121 cancels as w^4):
#define C1S 1.4641f      /* C1 * 121^2 */
#define C2S 13.1769f     /* C2 * 121^2 */

__device__ float    g_partials[NBLOCKS];
__device__ unsigned g_count;            // zero-initialized; self-resets each launch

typedef unsigned long long u64;
union F2 { u64 u; float2 f; };

__device__ __forceinline__ u64 f2add(u64 a, u64 b) {
    u64 d; asm("add.rn.f32x2 %0,%1,%2;" : "=l"(d) : "l"(a), "l"(b)); return d;
}
__device__ __forceinline__ u64 f2mul(u64 a, u64 b) {
    u64 d; asm("mul.rn.f32x2 %0,%1,%2;" : "=l"(d) : "l"(a), "l"(b)); return d;
}
__device__ __forceinline__ u64 f2fma(u64 a, u64 b, u64 c) {
    u64 d; asm("fma.rn.f32x2 %0,%1,%2,%3;" : "=l"(d) : "l"(a), "l"(b), "l"(c)); return d;
}

__device__ __forceinline__ u64 ldpair(const float* __restrict__ row, int c, bool ok) {
    F2 t;
    t.f = ok ? *reinterpret_cast<const float2*>(row + c) : make_float2(0.f, 0.f);
    return t.u;
}

// Vertical sliding-sum update for one input row (packed f32x2, 3 column pairs).
template <int SGN>
__device__ __forceinline__ void vupdate(u64 vs[5][3],
                                        const float* __restrict__ xrow,
                                        const float* __restrict__ yrow,
                                        int cb) {
    const u64 NEG1 = 0xBF800000BF800000ULL;   // packed (-1.f, -1.f)
    #pragma unroll
    for (int k = 0; k < 3; ++k) {
        int c = cb + 2 * k;                    // cb even -> pairs never straddle 0/512
        bool ok = ((unsigned)c < (unsigned)WW);
        u64 xv = ldpair(xrow, c, ok);
        u64 yv = ldpair(yrow, c, ok);
        if (SGN > 0) {
            vs[0][k] = f2add(vs[0][k], xv);
            vs[1][k] = f2add(vs[1][k], yv);
            vs[2][k] = f2fma(xv, xv, vs[2][k]);
            vs[3][k] = f2fma(yv, yv, vs[3][k]);
            vs[4][k] = f2fma(xv, yv, vs[4][k]);
        } else {
            u64 nx = f2mul(xv, NEG1);
            u64 ny = f2mul(yv, NEG1);
            vs[0][k] = f2add(vs[0][k], nx);
            vs[1][k] = f2add(vs[1][k], ny);
            vs[2][k] = f2fma(xv, nx, vs[2][k]);
            vs[3][k] = f2fma(yv, ny, vs[3][k]);
            vs[4][k] = f2fma(xv, ny, vs[4][k]);
        }
    }
}

__global__ __launch_bounds__(NT)
void ssim_kernel(const float* __restrict__ X, const float* __restrict__ Y,
                 float* __restrict__ out) {
    const int wid  = threadIdx.x >> 5;
    const int lane = threadIdx.x & 31;
    const int gw   = blockIdx.x * (NT / 32) + wid;

    const int s = gw % NSTRIP;          // column strip 0..2
    const int t = gw / NSTRIP;          // (z, rowtile)
    const int z = t >> 4;
    const int row0 = (t & (ROWTILES - 1)) * TILE_H;

    // Strip geometry: outputs [Ostart,Oend); warp computes vsums for 192
    // columns starting at V0 (covers all 11-tap windows + halo).
    const int Ostart = (s == 0) ? 0   : (s == 1 ? 172 : 342);
    const int Oend   = (s == 0) ? 172 : (s == 1 ? 342 : 512);
    const int V0     = (s == 2) ? 336 : Ostart - 8;

    const int cb = V0 + lane * 6;       // first vsum column of this lane (even)
    const float* __restrict__ Xz = X + (size_t)z * HH * WW;
    const float* __restrict__ Yz = Y + (size_t)z * HH * WW;

    // Vertical sliding sums: 5 channels x 3 packed column pairs (6 cols).
    u64 vs[5][3];
    #pragma unroll
    for (int ch = 0; ch < 5; ++ch)
        #pragma unroll
        for (int k = 0; k < 3; ++k) vs[ch][k] = 0ULL;

    // Prologue: rows [row0-5, row0+4] clamped to the image.
    #pragma unroll 1
    for (int rr = row0 - PAD; rr < row0 + PAD; ++rr) {
        if (rr < 0 || rr >= HH) continue;
        vupdate<+1>(vs, Xz + (size_t)rr * WW, Yz + (size_t)rr * WW, cb);
    }

    float partial = 0.f;

    #pragma unroll 1
    for (int r = row0; r < row0 + TILE_H; ++r) {
        int rn = r + PAD;
        if (rn < HH)
            vupdate<+1>(vs, Xz + (size_t)rn * WW, Yz + (size_t)rn * WW, cb);
        int ro = r - PAD - 1;
        if (r > row0 && ro >= 0)
            vupdate<-1>(vs, Xz + (size_t)ro * WW, Yz + (size_t)ro * WW, cb);

        // Horizontal 11-tap sums via warp shuffles (no shared memory).
        // win[16] covers columns cb-5 .. cb+10 for 6 outputs cb..cb+5.
        float Hs[5][6];
        #pragma unroll
        for (int ch = 0; ch < 5; ++ch) {
            float v[6];
            #pragma unroll
            for (int k = 0; k < 3; ++k) {
                F2 tt; tt.u = vs[ch][k];
                v[2 * k] = tt.f.x; v[2 * k + 1] = tt.f.y;
            }
            float win[16];
            #pragma unroll
            for (int k = 0; k < 5; ++k)
                win[k] = __shfl_up_sync(0xFFFFFFFFu, v[k + 1], 1);
            #pragma unroll
            for (int j = 0; j < 6; ++j) win[5 + j] = v[j];
            #pragma unroll
            for (int k = 0; k < 5; ++k)
                win[11 + k] = __shfl_down_sync(0xFFFFFFFFu, v[k], 1);

            float h = 0.f;
            #pragma unroll
            for (int k = 0; k < 11; ++k) h += win[k];
            Hs[ch][0] = h;
            #pragma unroll
            for (int j = 1; j < 6; ++j) {
                h += win[10 + j] - win[j - 1];
                Hs[ch][j] = h;
            }
        }

        // SSIM in raw-sum space (scale factor w^4 cancels between num/den).
        #pragma unroll
        for (int j = 0; j < 6; ++j) {
            float Sx  = Hs[0][j], Sy  = Hs[1][j];
            float Sxx = Hs[2][j], Syy = Hs[3][j], Sxy = Hs[4][j];
            float P  = Sx * Sy;
            float Q  = fmaf(Sx, Sx, Sy * Sy);
            float n1 = fmaf(2.f, P, C1S);
            float n2 = fmaf(-2.f, P, fmaf(242.f, Sxy, C2S));
            float d1 = Q + C1S;
            float d2 = fmaf(121.f, Sxx + Syy, C2S - Q);
            float vv = __fdividef(n1 * n2, d1 * d2);
            int c = cb + j;
            if (c >= Ostart && c < Oend) partial += vv;
        }
    }

    // Warp reduce, then one partial per block.
    #pragma unroll
    for (int off = 16; off > 0; off >>= 1)
        partial += __shfl_xor_sync(0xFFFFFFFFu, partial, off);
    __shared__ float wsum[NT / 32];
    __shared__ bool  s_last;
    if (lane == 0) wsum[wid] = partial;
    __syncthreads();
    if (threadIdx.x == 0) {
        g_partials[blockIdx.x] = wsum[0] + wsum[1] + wsum[2] + wsum[3];
        __threadfence();
        unsigned prev = atomicAdd(&g_count, 1u);
        s_last = (prev == NBLOCKS - 1);
    }
    __syncthreads();

    // Last block finalizes: sum all 768 partials with one warp.
    if (s_last && threadIdx.x < 32) {
        const float4* p = (const float4*)g_partials;
        double sum = 0.0;
        #pragma unroll
        for (int i = 0; i < NBLOCKS / 4 / 32; ++i) {   // 6 float4 per lane
            float4 v = p[threadIdx.x + 32 * i];
            sum += (double)v.x + (double)v.y + (double)v.z + (double)v.w;
        }
        #pragma unroll
        for (int off = 16; off > 0; off >>= 1)
            sum += __shfl_xor_sync(0xFFFFFFFFu, sum, off);
        if (threadIdx.x == 0) {
            out[0] = (float)(1.0 - sum / (double)((size_t)DZ * HH * WW));
            g_count = 0;               // reset for the next (graph-replayed) launch
        }
    }
}

extern "C" void kernel_launch(void* const* d_in, const int* in_sizes, int n_in,
                              void* d_out, int out_size) {
    const float* x = (const float*)d_in[0];
    const float* y = (const float*)d_in[1];
    float* out = (float*)d_out;

    ssim_kernel<<<NBLOCKS, NT>>>(x, y, out);
}